// round 2
// baseline (speedup 1.0000x reference)
#include <cuda_runtime.h>
#include <cuda_bf16.h>

#define NBLK 1024
#define NTHR 128

// Per-block partials + completion ticket (module-scope device memory; no allocs).
__device__ float g_sum[NBLK];
__device__ int   g_cnt[NBLK];
__device__ float g_max[NBLK];
__device__ unsigned int g_done = 0;

__device__ __forceinline__ void point_acc(float x, float y, float z,
                                          float& acc_sum, int& acc_cnt, float& acc_max) {
    // Fold into positive octant: octahedron |x|+|y|+|z| <= 1 is sign-symmetric.
    float qx = fabsf(x), qy = fabsf(y), qz = fabsf(z);
    float x2 = x * x, y2 = y * y, z2 = z * z;   // |.| free under squaring
    float s  = qx + qy + qz;

    // inside test: max over the 8 faces of p.n - off = s*c - c, c = fp32(1/sqrt(3))
    const float C = 0.57735026918962576f;
    bool inside = fmaf(s, C, -C) <= 1e-8f;

    // nearest-vertex distance^2 (vertices are +-e_i): |p|^2 + 1 - 2*max|p_i|
    float dot = x2 + y2 + z2;
    float mv  = fmaxf(qx, fmaxf(qy, qz));
    float d2v = fmaf(-2.0f, mv, dot + 1.0f);

    // face (plane) distance^2, valid when the projection lands inside the triangle
    float t1      = s - 1.0f;
    float face_sq = (t1 * t1) * (1.0f / 3.0f);
    float qmin    = fminf(qx, fminf(qy, qz));
    bool  face_ok = (3.0f * qmin >= t1);

    // Edge interior distance: for edge (e_i, e_j), t in (0,1) <=> |q_i - q_j| < 1,
    // and then both in-plane residuals equal m = (q_i + q_j - 1)/2:
    //   d^2 = 2 m^2 + q_k^2.
    // If t clamps, the true value is a vertex distance >= d2v, so fall back to d2v.
    float mxy = fmaf(0.5f, qx + qy, -0.5f);
    float exy = fmaf(2.0f * mxy, mxy, z2);
    exy = (fabsf(qx - qy) < 1.0f) ? exy : d2v;

    float myz = fmaf(0.5f, qy + qz, -0.5f);
    float eyz = fmaf(2.0f * myz, myz, x2);
    eyz = (fabsf(qy - qz) < 1.0f) ? eyz : d2v;

    float mzx = fmaf(0.5f, qz + qx, -0.5f);
    float ezx = fmaf(2.0f * mzx, mzx, y2);
    ezx = (fabsf(qz - qx) < 1.0f) ? ezx : d2v;

    float sq = fminf(exy, fminf(eyz, ezx));
    sq = face_ok ? face_sq : sq;

    acc_sum += inside ? d2v : 0.0f;
    acc_cnt += inside ? 1 : 0;
    acc_max  = fmaxf(acc_max, inside ? 0.0f : sq);
}

__device__ __forceinline__ void item4_acc(float4 f0, float4 f1, float4 f2,
                                          float& acc_sum, int& acc_cnt, float& acc_max) {
    point_acc(f0.x, f0.y, f0.z, acc_sum, acc_cnt, acc_max);
    point_acc(f0.w, f1.x, f1.y, acc_sum, acc_cnt, acc_max);
    point_acc(f1.z, f1.w, f2.x, acc_sum, acc_cnt, acc_max);
    point_acc(f2.y, f2.z, f2.w, acc_sum, acc_cnt, acc_max);
}

__global__ void __launch_bounds__(NTHR)
palette_bound_loss_kernel(const float4* __restrict__ pts4,
                          const float*  __restrict__ pts,
                          float* __restrict__ out,
                          int n_items, int n_points) {
    float acc_sum = 0.0f;
    int   acc_cnt = 0;
    float acc_max = 0.0f;

    const int nthreads = gridDim.x * blockDim.x;
    int item = blockIdx.x * blockDim.x + threadIdx.x;

    // Unroll-2 with all 6 float4 loads front-batched (MLP=6).
    for (; item + nthreads < n_items; item += 2 * nthreads) {
        const float4* ga = pts4 + 3 * item;
        const float4* gb = pts4 + 3 * (item + nthreads);
        float4 a0 = ga[0], a1 = ga[1], a2 = ga[2];
        float4 b0 = gb[0], b1 = gb[1], b2 = gb[2];
        item4_acc(a0, a1, a2, acc_sum, acc_cnt, acc_max);
        item4_acc(b0, b1, b2, acc_sum, acc_cnt, acc_max);
    }
    for (; item < n_items; item += nthreads) {
        const float4* ga = pts4 + 3 * item;
        float4 a0 = ga[0], a1 = ga[1], a2 = ga[2];
        item4_acc(a0, a1, a2, acc_sum, acc_cnt, acc_max);
    }

    // warp reduce: 2 float shuffle trees + 1 hardware redux for the int count
    #pragma unroll
    for (int o = 16; o > 0; o >>= 1) {
        acc_sum += __shfl_down_sync(0xffffffffu, acc_sum, o);
        acc_max  = fmaxf(acc_max, __shfl_down_sync(0xffffffffu, acc_max, o));
    }
    acc_cnt = __reduce_add_sync(0xffffffffu, acc_cnt);

    __shared__ float s_sum[NTHR / 32];
    __shared__ int   s_cnt[NTHR / 32];
    __shared__ float s_max[NTHR / 32];
    int lane = threadIdx.x & 31;
    int wid  = threadIdx.x >> 5;
    if (lane == 0) { s_sum[wid] = acc_sum; s_cnt[wid] = acc_cnt; s_max[wid] = acc_max; }
    __syncthreads();

    __shared__ bool s_is_last;
    if (threadIdx.x == 0) {
        float bs = 0.0f; int bc = 0; float bm = 0.0f;
        #pragma unroll
        for (int i = 0; i < NTHR / 32; i++) {
            bs += s_sum[i]; bc += s_cnt[i]; bm = fmaxf(bm, s_max[i]);
        }
        g_sum[blockIdx.x] = bs;
        g_cnt[blockIdx.x] = bc;
        g_max[blockIdx.x] = bm;
        __threadfence();
        unsigned int ticket = atomicAdd(&g_done, 1u);
        s_is_last = (ticket == (unsigned int)(gridDim.x - 1));
    }
    __syncthreads();

    if (s_is_last) {
        __threadfence();  // acquire side: partials from all blocks are visible
        float fs = 0.0f; int fc = 0; float fm = 0.0f;
        for (int i = threadIdx.x; i < NBLK; i += NTHR) {
            fs += g_sum[i]; fc += g_cnt[i]; fm = fmaxf(fm, g_max[i]);
        }
        #pragma unroll
        for (int o = 16; o > 0; o >>= 1) {
            fs += __shfl_down_sync(0xffffffffu, fs, o);
            fm  = fmaxf(fm, __shfl_down_sync(0xffffffffu, fm, o));
        }
        fc = __reduce_add_sync(0xffffffffu, fc);
        if (lane == 0) { s_sum[wid] = fs; s_cnt[wid] = fc; s_max[wid] = fm; }
        __syncthreads();
        if (threadIdx.x == 0) {
            float fs2 = 0.0f; int fc2 = 0; float fm2 = 0.0f;
            #pragma unroll
            for (int i = 0; i < NTHR / 32; i++) {
                fs2 += s_sum[i]; fc2 += s_cnt[i]; fm2 = fmaxf(fm2, s_max[i]);
            }
            // scalar tail (n_points % 4), normally empty for N = 1048576
            for (int p = n_items * 4; p < n_points; p++) {
                point_acc(pts[3 * p + 0], pts[3 * p + 1], pts[3 * p + 2], fs2, fc2, fm2);
            }
            int n_out = n_points - fc2;
            float loss_in  = (fc2   > 0) ? (0.001f * fs2 / (float)fc2) : 0.0f;
            float loss_out = (n_out > 0) ? fm2 : 0.0f;
            out[0] = loss_in + loss_out;
            g_done = 0;  // reset ticket so every graph replay starts clean
        }
    }
}

extern "C" void kernel_launch(void* const* d_in, const int* in_sizes, int n_in,
                              void* d_out, int out_size) {
    const float* pts = (const float*)d_in[0];
    int n_points = in_sizes[0] / 3;
    int n_items  = n_points / 4;   // 4 points (12 floats = 3 float4) per work item
    palette_bound_loss_kernel<<<NBLK, NTHR>>>(
        (const float4*)pts, pts, (float*)d_out, n_items, n_points);
}

// round 3
// speedup vs baseline: 1.1682x; 1.1682x over previous
#include <cuda_runtime.h>
#include <cuda_bf16.h>

#define NBLK 1024
#define NTHR 256

// Per-block partials + completion ticket (module-scope device memory; no allocs).
__device__ float g_sum[NBLK];
__device__ int   g_cnt[NBLK];
__device__ float g_max[NBLK];
__device__ unsigned int g_done = 0;

__device__ __forceinline__ void point_acc(float x, float y, float z,
                                          float& acc_sum, int& acc_cnt, float& acc_max) {
    // Fold into positive octant: octahedron |x|+|y|+|z| <= 1 is sign-symmetric.
    // fabsf folds into FADD/FMNMX operand modifiers (free).
    float qx = fabsf(x), qy = fabsf(y), qz = fabsf(z);
    float s   = qx + qy + qz;
    float x2  = x * x, y2 = y * y, z2 = z * z;
    float dot = fmaf(x, x, fmaf(y, y, z * z));

    const float C = 0.57735026918962576f;           // fp32(1/sqrt(3))
    bool inside = (s * C - C) <= 1e-8f;             // same arithmetic as reference

    float mx  = fmaxf(qx, fmaxf(qy, qz));           // largest |coord|
    float mn  = fminf(qx, fminf(qy, qz));           // smallest
    float mn2 = fminf(x2, fminf(y2, z2));           // mn^2 without an extra mul

    // nearest-vertex distance^2 = (mx-1)^2 + md^2 + mn^2 = dot + 1 - 2*mx
    float dp1 = dot + 1.0f;
    float d2v = fmaf(-2.0f, mx, dp1);

    if (inside) {
        acc_sum += d2v;
        acc_cnt += 1;
    } else {
        // Exact distance^2 to the simplex {x>=0, sum=1} via sorted threshold cascade.
        float t1      = s - 1.0f;
        float face_sq = (t1 * (1.0f / 3.0f)) * t1;  // 3*tau3^2
        bool  face_ok = (3.0f * mn >= t1);          // mn >= tau3

        float tau2 = fmaf(0.5f, s - mn, -0.5f);     // (s - mn - 1)/2
        float e    = fmaf(tau2 + tau2, tau2, mn2);  // 2*tau2^2 + mn^2
        // edge valid iff md >= tau2  <=>  s + 1 >= 2*mx + mn  (md = s - mx - mn)
        float sp1     = s + 1.0f;
        bool  edge_ok = fmaf(-2.0f, mx, sp1) >= mn;

        float sq = edge_ok ? e : d2v;               // vertex fallback == d2v (identity)
        sq = face_ok ? face_sq : sq;
        acc_max = fmaxf(acc_max, sq);
    }
}

__global__ void __launch_bounds__(NTHR, 8)
palette_bound_loss_kernel(const float4* __restrict__ pts4,
                          const float*  __restrict__ pts,
                          float* __restrict__ out,
                          int n_items, int n_points) {
    float acc_sum = 0.0f;
    int   acc_cnt = 0;
    float acc_max = 0.0f;

    const int nthreads = gridDim.x * blockDim.x;
    for (int item = blockIdx.x * blockDim.x + threadIdx.x; item < n_items; item += nthreads) {
        // 3 x float4 = 12 floats = 4 points, fully coalesced, MLP=3
        const float4* g = pts4 + 3 * item;
        float4 f0 = g[0], f1 = g[1], f2 = g[2];
        point_acc(f0.x, f0.y, f0.z, acc_sum, acc_cnt, acc_max);
        point_acc(f0.w, f1.x, f1.y, acc_sum, acc_cnt, acc_max);
        point_acc(f1.z, f1.w, f2.x, acc_sum, acc_cnt, acc_max);
        point_acc(f2.y, f2.z, f2.w, acc_sum, acc_cnt, acc_max);
    }

    // warp reduce: 2 float shuffle trees + hardware redux for the int count
    #pragma unroll
    for (int o = 16; o > 0; o >>= 1) {
        acc_sum += __shfl_down_sync(0xffffffffu, acc_sum, o);
        acc_max  = fmaxf(acc_max, __shfl_down_sync(0xffffffffu, acc_max, o));
    }
    acc_cnt = __reduce_add_sync(0xffffffffu, acc_cnt);

    __shared__ float s_sum[NTHR / 32];
    __shared__ int   s_cnt[NTHR / 32];
    __shared__ float s_max[NTHR / 32];
    int lane = threadIdx.x & 31;
    int wid  = threadIdx.x >> 5;
    if (lane == 0) { s_sum[wid] = acc_sum; s_cnt[wid] = acc_cnt; s_max[wid] = acc_max; }
    __syncthreads();

    __shared__ bool s_is_last;
    if (threadIdx.x == 0) {
        float bs = 0.0f; int bc = 0; float bm = 0.0f;
        #pragma unroll
        for (int i = 0; i < NTHR / 32; i++) {
            bs += s_sum[i]; bc += s_cnt[i]; bm = fmaxf(bm, s_max[i]);
        }
        g_sum[blockIdx.x] = bs;
        g_cnt[blockIdx.x] = bc;
        g_max[blockIdx.x] = bm;
        __threadfence();
        unsigned int ticket = atomicAdd(&g_done, 1u);
        s_is_last = (ticket == (unsigned int)(gridDim.x - 1));
    }
    __syncthreads();

    if (s_is_last) {
        __threadfence();  // acquire side: all blocks' partials visible
        float fs = 0.0f; int fc = 0; float fm = 0.0f;
        for (int i = threadIdx.x; i < NBLK; i += NTHR) {
            fs += g_sum[i]; fc += g_cnt[i]; fm = fmaxf(fm, g_max[i]);
        }
        #pragma unroll
        for (int o = 16; o > 0; o >>= 1) {
            fs += __shfl_down_sync(0xffffffffu, fs, o);
            fm  = fmaxf(fm, __shfl_down_sync(0xffffffffu, fm, o));
        }
        fc = __reduce_add_sync(0xffffffffu, fc);
        if (lane == 0) { s_sum[wid] = fs; s_cnt[wid] = fc; s_max[wid] = fm; }
        __syncthreads();
        if (threadIdx.x == 0) {
            float fs2 = 0.0f; int fc2 = 0; float fm2 = 0.0f;
            #pragma unroll
            for (int i = 0; i < NTHR / 32; i++) {
                fs2 += s_sum[i]; fc2 += s_cnt[i]; fm2 = fmaxf(fm2, s_max[i]);
            }
            // scalar tail (n_points % 4), normally empty for N = 1048576
            for (int p = n_items * 4; p < n_points; p++) {
                point_acc(pts[3 * p + 0], pts[3 * p + 1], pts[3 * p + 2], fs2, fc2, fm2);
            }
            int n_out = n_points - fc2;
            float loss_in  = (fc2   > 0) ? (0.001f * fs2 / (float)fc2) : 0.0f;
            float loss_out = (n_out > 0) ? fm2 : 0.0f;
            out[0] = loss_in + loss_out;
            g_done = 0;  // reset ticket so every graph replay starts clean
        }
    }
}

extern "C" void kernel_launch(void* const* d_in, const int* in_sizes, int n_in,
                              void* d_out, int out_size) {
    const float* pts = (const float*)d_in[0];
    int n_points = in_sizes[0] / 3;
    int n_items  = n_points / 4;   // 4 points (12 floats = 3 float4) per work item
    palette_bound_loss_kernel<<<NBLK, NTHR>>>(
        (const float4*)pts, pts, (float*)d_out, n_items, n_points);
}